// round 4
// baseline (speedup 1.0000x reference)
#include <cuda_runtime.h>
#include <math.h>

#define Bz   64
#define Lz   49
#define ENCD 2048
#define DEC  512
#define ATTD 256
#define VOC  10000
#define Tz   50
#define H3   1536
#define EMBD 512

// ---------------- scratch (device globals; no runtime alloc) ----------------
__device__ float g_enc [Bz*Lz*DEC];     // [B,L,DEC]
__device__ float g_att1[Bz*Lz*ATTD];    // [B,L,ATT]
__device__ float g_Xemb[Tz*Bz*EMBD];    // gathered embeddings, row r = t*B+b
__device__ float g_gie [Tz*Bz*H3];      // emb part of GRU input gates (+b_ih)
__device__ float g_Wihe[DEC*H3];        // W_ih[:, :512]  transposed -> [k][j]
__device__ float g_Wihc[DEC*H3];        // W_ih[:, 512:]  transposed -> [k][j]
__device__ float g_Whh [DEC*H3];        // W_hh transposed -> [k][j]
__device__ float g_h   [Bz*DEC];        // current hidden
__device__ float g_ctx [Bz*DEC];        // attention context
__device__ float g_part[8*Bz*H3];       // split-K partials: [mat(2)*4+split][b][j]
__device__ float g_Hseq[Tz*Bz*DEC];     // h_new per step, row r = t*B+b

// ---------------- init: zero h + gather embeddings ----------------
__global__ void k_init(const int* __restrict__ cap, const float* __restrict__ emb)
{
    int i = blockIdx.x * blockDim.x + threadIdx.x;   // launched with exactly T*B*EMB threads
    if (i < Bz * DEC) g_h[i] = 0.f;
    int d = i & 511;
    int r = i >> 9;            // t*B + b
    int t = r >> 6;
    int b = r & 63;
    int tok = cap[b * Tz + t];
    g_Xemb[i] = emb[(size_t)tok * EMBD + d];
}

// ---------------- one-time weight transposes ----------------
__global__ void k_transpose(const float* __restrict__ W_ih, const float* __restrict__ W_hh)
{
    int i = blockIdx.x * blockDim.x + threadIdx.x;   // over DEC*H3
    if (i >= DEC * H3) return;
    int j = i >> 9;       // 0..1535 (row of torch weight)
    int k = i & 511;      // 0..511
    g_Wihe[k * H3 + j] = W_ih[j * (EMBD + DEC) + k];
    g_Wihc[k * H3 + j] = W_ih[j * (EMBD + DEC) + EMBD + k];
    g_Whh [k * H3 + j] = W_hh[j * DEC + k];
}

// ---------------- generic fp32 GEMM: C[M,N] = A[M,K] @ B[K,N] + bias ----------------
// 128x128 block tile, 8x8 microtile, 256 threads. remap=1 writes fc output as
// out[(b*T + t)*V + n] with row = t*B + b.
__global__ __launch_bounds__(256) void k_gemm(
    const float* __restrict__ A, const float* __restrict__ Bm,
    const float* __restrict__ bias, float* __restrict__ C,
    int M, int N, int K, int remap)
{
    __shared__ float sA[16][132];
    __shared__ float sB[16][128];
    const int tid = threadIdx.x;
    const int tx = tid & 15, ty = tid >> 4;
    const int mb = blockIdx.y << 7;
    const int nb = blockIdx.x << 7;
    float acc[8][8] = {};

    for (int k0 = 0; k0 < K; k0 += 16) {
        #pragma unroll
        for (int u = 0; u < 2; u++) {
            int f = tid + u * 256;
            // A tile: 128 rows x 16 k  (512 float4)
            int arow = f >> 2, akq = (f & 3) << 2;
            float4 av = make_float4(0.f, 0.f, 0.f, 0.f);
            if (mb + arow < M)
                av = *reinterpret_cast<const float4*>(&A[(size_t)(mb + arow) * K + k0 + akq]);
            sA[akq + 0][arow] = av.x; sA[akq + 1][arow] = av.y;
            sA[akq + 2][arow] = av.z; sA[akq + 3][arow] = av.w;
            // B tile: 16 rows x 128 cols (512 float4), guard N
            int brow = f >> 5, bcol = (f & 31) << 2;
            int n = nb + bcol;
            const float* bp = &Bm[(size_t)(k0 + brow) * N + n];
            float4 bv;
            if (n + 3 < N) bv = *reinterpret_cast<const float4*>(bp);
            else {
                bv.x = (n + 0 < N) ? bp[0] : 0.f;
                bv.y = (n + 1 < N) ? bp[1] : 0.f;
                bv.z = (n + 2 < N) ? bp[2] : 0.f;
                bv.w = (n + 3 < N) ? bp[3] : 0.f;
            }
            *reinterpret_cast<float4*>(&sB[brow][bcol]) = bv;
        }
        __syncthreads();
        #pragma unroll
        for (int kk = 0; kk < 16; kk++) {
            float4 a0 = *reinterpret_cast<const float4*>(&sA[kk][ty * 8]);
            float4 a1 = *reinterpret_cast<const float4*>(&sA[kk][ty * 8 + 4]);
            float4 b0 = *reinterpret_cast<const float4*>(&sB[kk][tx * 8]);
            float4 b1 = *reinterpret_cast<const float4*>(&sB[kk][tx * 8 + 4]);
            float av[8] = {a0.x, a0.y, a0.z, a0.w, a1.x, a1.y, a1.z, a1.w};
            float bv[8] = {b0.x, b0.y, b0.z, b0.w, b1.x, b1.y, b1.z, b1.w};
            #pragma unroll
            for (int i = 0; i < 8; i++)
                #pragma unroll
                for (int j = 0; j < 8; j++)
                    acc[i][j] += av[i] * bv[j];
        }
        __syncthreads();
    }

    #pragma unroll
    for (int i = 0; i < 8; i++) {
        int row = mb + ty * 8 + i;
        if (row >= M) break;
        #pragma unroll
        for (int j = 0; j < 8; j++) {
            int col = nb + tx * 8 + j;
            if (col < N) {
                float v = acc[i][j] + bias[col];
                if (remap) {
                    int t = row >> 6, bb = row & 63;
                    C[((size_t)(bb * Tz + t)) * VOC + col] = v;
                } else {
                    C[(size_t)row * N + col] = v;
                }
            }
        }
    }
}

// ---------------- per-step dual GEMM (gi_c and gh), split-K=4 ----------------
// grid (24 n-tiles, 4 k-splits, 2 mats), block 256. Each block: 64x64x128.
__global__ __launch_bounds__(256) void k_stepgemm()
{
    __shared__ float sA[16][68];
    __shared__ float sB[16][64];
    const int tid = threadIdx.x;
    const int tx = tid & 15, ty = tid >> 4;
    const int nb = blockIdx.x << 6;
    const int kbase = blockIdx.y << 7;
    const int z = blockIdx.z;
    const float* A  = z ? g_h   : g_ctx;
    const float* Bw = z ? g_Whh : g_Wihc;
    float* out = &g_part[(size_t)((z * 4 + blockIdx.y) * Bz) * H3];
    float acc[4][4] = {};
    const int arow = tid >> 2, akq = (tid & 3) << 2;
    const int brow = tid >> 4, bcol = (tid & 15) << 2;

    for (int kc = 0; kc < 128; kc += 16) {
        int k0 = kbase + kc;
        float4 av = *reinterpret_cast<const float4*>(&A[arow * DEC + k0 + akq]);
        sA[akq + 0][arow] = av.x; sA[akq + 1][arow] = av.y;
        sA[akq + 2][arow] = av.z; sA[akq + 3][arow] = av.w;
        float4 bv = *reinterpret_cast<const float4*>(&Bw[(size_t)(k0 + brow) * H3 + nb + bcol]);
        *reinterpret_cast<float4*>(&sB[brow][bcol]) = bv;
        __syncthreads();
        #pragma unroll
        for (int kk = 0; kk < 16; kk++) {
            float4 a = *reinterpret_cast<const float4*>(&sA[kk][ty * 4]);
            float4 b = *reinterpret_cast<const float4*>(&sB[kk][tx * 4]);
            float avr[4] = {a.x, a.y, a.z, a.w};
            float bvr[4] = {b.x, b.y, b.z, b.w};
            #pragma unroll
            for (int i = 0; i < 4; i++)
                #pragma unroll
                for (int j = 0; j < 4; j++)
                    acc[i][j] += avr[i] * bvr[j];
        }
        __syncthreads();
    }
    #pragma unroll
    for (int i = 0; i < 4; i++)
        #pragma unroll
        for (int j = 0; j < 4; j++)
            out[(size_t)(ty * 4 + i) * H3 + nb + tx * 4 + j] = acc[i][j];
}

// ---------------- GRU gate combine (reads split-K partials) ----------------
__device__ __forceinline__ float gru_update(int r, int b, int d, const float* __restrict__ b_hh)
{
    const float* gie = &g_gie[(size_t)r * H3];
    float ir = gie[d], iz = gie[DEC + d], in_ = gie[2 * DEC + d];
    float hr = b_hh[d], hz = b_hh[DEC + d], hn = b_hh[2 * DEC + d];
    #pragma unroll
    for (int s = 0; s < 4; s++) {
        const float* p = &g_part[(size_t)(s * Bz + b) * H3];
        ir += p[d]; iz += p[DEC + d]; in_ += p[2 * DEC + d];
        const float* q = &g_part[(size_t)((4 + s) * Bz + b) * H3];
        hr += q[d]; hz += q[DEC + d]; hn += q[2 * DEC + d];
    }
    float rr = 1.f / (1.f + expf(-(ir + hr)));
    float zz = 1.f / (1.f + expf(-(iz + hz)));
    float nn = tanhf(in_ + rr * hn);
    float hp = g_h[b * DEC + d];
    return (1.f - zz) * nn + zz * hp;
}

// ---------------- fused: gates(t-1) -> h_t, then Bahdanau attention(h_t) ----------------
// grid 16 blocks x 4 batch rows, 256 threads.
__global__ __launch_bounds__(256) void k_att(
    int t,
    const float* __restrict__ W_da, const float* __restrict__ b_da,
    const float* __restrict__ W_fa, const float* __restrict__ b_hh)
{
    __shared__ float sh_h [4][DEC];
    __shared__ float sh_a2[4][ATTD];
    __shared__ float sh_sc[4][64];
    const int tid = threadIdx.x;
    const int b0 = blockIdx.x << 2;

    if (t > 0) {
        #pragma unroll
        for (int ii = 0; ii < 8; ii++) {
            int idx = tid + (ii << 8);          // 0..2047
            int bi = idx >> 9, d = idx & 511;
            int b = b0 + bi;
            int r = (t - 1) * Bz + b;
            float hv = gru_update(r, b, d, b_hh);
            sh_h[bi][d] = hv;
            g_h[b * DEC + d] = hv;
            g_Hseq[(size_t)r * DEC + d] = hv;
        }
    } else {
        #pragma unroll
        for (int ii = 0; ii < 8; ii++) {
            int idx = tid + (ii << 8);
            sh_h[idx >> 9][idx & 511] = 0.f;
        }
    }
    __syncthreads();

    // att2[bi][j] = h[bi] @ W_da[:,j] + b_da[j]   (thread j handles all 4 bi)
    {
        int j = tid;
        float a0 = b_da[j], a1 = a0, a2 = a0, a3 = a0;
        #pragma unroll 8
        for (int k = 0; k < DEC; k++) {
            float w = W_da[k * ATTD + j];
            a0 += sh_h[0][k] * w;
            a1 += sh_h[1][k] * w;
            a2 += sh_h[2][k] * w;
            a3 += sh_h[3][k] * w;
        }
        sh_a2[0][j] = a0; sh_a2[1][j] = a1; sh_a2[2][j] = a2; sh_a2[3][j] = a3;
    }
    __syncthreads();

    // scores: warp per (bi,l) pair; lane sums 8 of the 256 ATT dims
    {
        int warp = tid >> 5, lane = tid & 31;
        float wfa[8];
        #pragma unroll
        for (int q = 0; q < 8; q++) wfa[q] = W_fa[lane + 32 * q];
        for (int p = warp; p < 4 * Lz; p += 8) {
            int bi = p / Lz, l = p % Lz;
            const float* arow = &g_att1[((size_t)(b0 + bi) * Lz + l) * ATTD];
            float s = 0.f;
            #pragma unroll
            for (int q = 0; q < 8; q++) {
                int j = lane + 32 * q;
                s += tanhf(arow[j] + sh_a2[bi][j]) * wfa[q];
            }
            #pragma unroll
            for (int o = 16; o; o >>= 1) s += __shfl_xor_sync(0xffffffffu, s, o);
            if (lane == 0) sh_sc[bi][l] = s;
        }
    }
    __syncthreads();

    // softmax over L=49 (b_fa shift is softmax-invariant)
    if (tid < 4) {
        float mx = -1e30f;
        for (int l = 0; l < Lz; l++) mx = fmaxf(mx, sh_sc[tid][l]);
        float sum = 0.f;
        for (int l = 0; l < Lz; l++) { float e = expf(sh_sc[tid][l] - mx); sh_sc[tid][l] = e; sum += e; }
        float inv = 1.f / sum;
        for (int l = 0; l < Lz; l++) sh_sc[tid][l] *= inv;
    }
    __syncthreads();

    // context[bi][d] = sum_l alpha[l] * enc[b,l,d]
    {
        int d = tid;  // handles d and d+256
        #pragma unroll
        for (int bi = 0; bi < 4; bi++) {
            const float* erow = &g_enc[(size_t)(b0 + bi) * Lz * DEC];
            float c0 = 0.f, c1 = 0.f;
            for (int l = 0; l < Lz; l++) {
                float al = sh_sc[bi][l];
                c0 += al * erow[l * DEC + d];
                c1 += al * erow[l * DEC + 256 + d];
            }
            g_ctx[(b0 + bi) * DEC + d]       = c0;
            g_ctx[(b0 + bi) * DEC + 256 + d] = c1;
        }
    }
}

// ---------------- final step's gate combine (t = T-1) ----------------
__global__ void k_gates(int t, const float* __restrict__ b_hh)
{
    int b = blockIdx.x, d = threadIdx.x;
    int r = t * Bz + b;
    float hv = gru_update(r, b, d, b_hh);
    g_h[b * DEC + d] = hv;
    g_Hseq[(size_t)r * DEC + d] = hv;
}

// ---------------- launcher ----------------
extern "C" void kernel_launch(void* const* d_in, const int* in_sizes, int n_in,
                              void* d_out, int out_size)
{
    (void)in_sizes; (void)n_in; (void)out_size;
    const float* spatial = (const float*)d_in[0];
    const int*   cap     = (const int*)  d_in[1];
    const float* W_feat  = (const float*)d_in[2];
    const float* b_feat  = (const float*)d_in[3];
    const float* W_ea    = (const float*)d_in[4];
    const float* b_ea    = (const float*)d_in[5];
    const float* W_da    = (const float*)d_in[6];
    const float* b_da    = (const float*)d_in[7];
    const float* W_fa    = (const float*)d_in[8];
    /* b_fa (d_in[9]) is softmax-invariant */
    const float* emb     = (const float*)d_in[10];
    const float* W_ih    = (const float*)d_in[11];
    const float* W_hh    = (const float*)d_in[12];
    const float* b_ih    = (const float*)d_in[13];
    const float* b_hh    = (const float*)d_in[14];
    const float* W_fc    = (const float*)d_in[15];
    const float* b_fc    = (const float*)d_in[16];
    float* out = (float*)d_out;

    float *p_enc, *p_att1, *p_xemb, *p_gie, *p_wihe, *p_hseq;
    cudaGetSymbolAddress((void**)&p_enc,  g_enc);
    cudaGetSymbolAddress((void**)&p_att1, g_att1);
    cudaGetSymbolAddress((void**)&p_xemb, g_Xemb);
    cudaGetSymbolAddress((void**)&p_gie,  g_gie);
    cudaGetSymbolAddress((void**)&p_wihe, g_Wihe);
    cudaGetSymbolAddress((void**)&p_hseq, g_Hseq);

    // setup
    k_init<<<Tz * Bz, EMBD>>>(cap, emb);                       // zero h + gather emb
    k_transpose<<<(DEC * H3 + 255) / 256, 256>>>(W_ih, W_hh);

    // big loop-invariant GEMMs
    k_gemm<<<dim3(4, 25), 256>>>(spatial, W_feat, b_feat, p_enc, Bz * Lz, DEC, ENCD, 0);
    k_gemm<<<dim3(2, 25), 256>>>(p_enc, W_ea, b_ea, p_att1, Bz * Lz, ATTD, DEC, 0);
    k_gemm<<<dim3(12, 25), 256>>>(p_xemb, p_wihe, b_ih, p_gie, Tz * Bz, H3, DEC, 0);

    // sequential decode: 2 nodes per step
    for (int t = 0; t < Tz; t++) {
        k_att<<<16, 256>>>(t, W_da, b_da, W_fa, b_hh);
        k_stepgemm<<<dim3(24, 4, 2), 256>>>();
    }
    k_gates<<<Bz, DEC>>>(Tz - 1, b_hh);                        // finalize h_{T-1} -> Hseq

    // one big fc GEMM over all timesteps, writes [B,T,V] directly
    k_gemm<<<dim3((VOC + 127) / 128, 25), 256>>>(p_hseq, W_fc, b_fc, out, Tz * Bz, VOC, DEC, 1);
}